// round 3
// baseline (speedup 1.0000x reference)
#include <cuda_runtime.h>

#define C    256
#define CH   128
#define HWn  262144
#define HW4  65536
#define SEGS 16
#define SEG_F4 4096   // HW4 / SEGS
#define EPS  1e-5f

// k3 tiling: 96 pixels per tile (384B contiguous per channel), double-buffered
#define TP      96
#define TP4     24
#define TILE_F  (C * TP)        // 24576 floats = 96 KB
#define TILE_F4 (TILE_F / 4)    // 6144
#define K3T     384             // threads in k3
#define NTILES  ((HW4 + TP4 - 1) / TP4)   // 2731 (last tile partial)

__device__ float d_partials[C * SEGS];
__device__ float d_g[C];
__device__ float d_v[C];
__device__ float d_b0;

// ---------------- Kernel 1: per-channel spatial sums (deterministic partials) ----
__global__ void k1_sums(const float4* __restrict__ x4) {
    const int c = blockIdx.y, seg = blockIdx.x, t = threadIdx.x;
    const float4* xc = x4 + (size_t)c * HW4 + (size_t)seg * SEG_F4;
    float s = 0.f;
#pragma unroll
    for (int j = 0; j < 16; j++) {
        float4 u = xc[t + j * 256];
        s += (u.x + u.y) + (u.z + u.w);
    }
    __shared__ float red[256];
    red[t] = s;
    __syncthreads();
    for (int off = 128; off > 0; off >>= 1) {
        if (t < off) red[t] += red[t + off];
        __syncthreads();
    }
    if (t == 0) d_partials[c * SEGS + seg] = red[0];
}

// ---------------- Kernel 2: all the tiny algebra (1 block) ------------------------
__global__ void k2_scalars(const float* __restrict__ cv1w, const float* __restrict__ cv1b,
                           const float* __restrict__ cv3w, const float* __restrict__ cv3b,
                           const float* __restrict__ lng,  const float* __restrict__ lnb,
                           const float* __restrict__ sp1w, const float* __restrict__ sp1b,
                           const float* __restrict__ sp2w, const float* __restrict__ sp2b) {
    __shared__ float S[C];
    __shared__ float ybuf[CH];
    __shared__ float s2[CH];
    __shared__ float wsm[CH];
    __shared__ float red[256];
    const int t = threadIdx.x;

    {
        float s = 0.f;
#pragma unroll
        for (int j = 0; j < SEGS; j++) s += d_partials[t * SEGS + j];
        S[t] = s;
    }
    __syncthreads();

    if (t < CH) {
        float a = 0.f;
        for (int c = 0; c < C; c++) a += cv1w[t * C + c] * S[c];
        ybuf[t] = a + (float)HWn * cv1b[t];
    } else {
        const int u = t - CH;
        float a = 0.f;
        for (int c = 0; c < C; c++) a += sp2w[u * C + c] * S[c];
        s2[u] = a * (1.f / (float)HWn) + sp2b[u];
    }
    __syncthreads();

    float zv = cv3b[t];
    for (int c = 0; c < CH; c++) zv += cv3w[t * CH + c] * ybuf[c];

    red[t] = zv;
    __syncthreads();
    for (int off = 128; off > 0; off >>= 1) {
        if (t < off) red[t] += red[t + off];
        __syncthreads();
    }
    const float mu = red[0] * (1.f / (float)C);
    __syncthreads();
    red[t] = zv * zv;
    __syncthreads();
    for (int off = 128; off > 0; off >>= 1) {
        if (t < off) red[t] += red[t + off];
        __syncthreads();
    }
    const float var = red[0] * (1.f / (float)C) - mu * mu;
    __syncthreads();

    const float zn = (zv - mu) * rsqrtf(var + EPS) * lng[t] + lnb[t];
    d_g[t] = 1.f / (1.f + expf(-zn));

    red[t] = (t < CH) ? s2[t] : -1e30f;
    __syncthreads();
    for (int off = 128; off > 0; off >>= 1) {
        if (t < off) red[t] = fmaxf(red[t], red[t + off]);
        __syncthreads();
    }
    const float mx = red[0];
    __syncthreads();
    red[t] = (t < CH) ? expf(s2[t] - mx) : 0.f;
    __syncthreads();
    for (int off = 128; off > 0; off >>= 1) {
        if (t < off) red[t] += red[t + off];
        __syncthreads();
    }
    const float denom = red[0];
    __syncthreads();
    if (t < CH) wsm[t] = expf(s2[t] - mx) / denom;
    __syncthreads();

    {
        float vv = 0.f;
        for (int c_ = 0; c_ < CH; c_++) vv += wsm[c_] * sp1w[c_ * C + t];
        d_v[t] = vv;
    }
    if (t == 0) {
        float b0 = 0.f;
        for (int c_ = 0; c_ < CH; c_++) b0 += wsm[c_] * sp1b[c_];
        d_b0 = b0;
    }
}

// ---------------- Kernel 3: pipelined fused yb + output (96-pixel tiles) ----------
__device__ __forceinline__ void k3_prefetch(const float4* __restrict__ x4,
                                            float* buf, int tile, int t) {
    unsigned dst_base = (unsigned)__cvta_generic_to_shared(buf);
    const int base4 = tile * TP4;
#pragma unroll
    for (int j = 0; j < 16; j++) {
        int i4 = t + j * K3T;
        int c = i4 / TP4, p4 = i4 % TP4;
        if (base4 + p4 < HW4) {
            const float4* src = x4 + (size_t)c * HW4 + base4 + p4;
            unsigned dst = dst_base + i4 * 16;
            asm volatile("cp.async.cg.shared.global [%0], [%1], 16;\n" :: "r"(dst), "l"(src));
        }
    }
    asm volatile("cp.async.commit_group;\n");
}

__global__ __launch_bounds__(K3T, 1)
void k3_out(const float4* __restrict__ x4, float4* __restrict__ out4,
            int grid_stride) {
    extern __shared__ float sm[];
    float* buf0 = sm;                    // TILE_F
    float* buf1 = sm + TILE_F;           // TILE_F
    float* sv   = sm + 2 * TILE_F;       // C
    float* sg   = sv + C;                // C
    float* part = sg + C;                // K3T
    float* sy   = part + K3T;            // TP

    const int t = threadIdx.x;
    if (t < C) { sv[t] = d_v[t]; sg[t] = d_g[t]; }
    const float b0 = d_b0;

    int tile = blockIdx.x;
    if (tile >= NTILES) return;
    k3_prefetch(x4, buf0, tile, t);

    int i = 0;
    while (tile < NTILES) {
        float* cur = (i & 1) ? buf1 : buf0;
        float* nxt = (i & 1) ? buf0 : buf1;
        const int ntile = tile + grid_stride;
        if (ntile < NTILES) {
            k3_prefetch(x4, nxt, ntile, t);
            asm volatile("cp.async.wait_group 1;\n");
        } else {
            asm volatile("cp.async.wait_group 0;\n");
        }
        __syncthreads();

        // yb partial dots: p = pixel (0..95), q = channel quarter (0..3)
        {
            const int p = t % TP, q = t / TP;
            float acc = 0.f;
            const float* tp_ = cur + (q * 64) * TP + p;
            const float* vp  = sv + q * 64;
#pragma unroll
            for (int c = 0; c < 64; c++) acc += vp[c] * tp_[c * TP];
            part[q * TP + p] = acc;
        }
        __syncthreads();
        if (t < TP) {
            float yb = b0 + part[t] + part[TP + t] + part[2 * TP + t] + part[3 * TP + t];
            sy[t] = 1.f / (1.f + expf(-yb));
        }
        __syncthreads();

        // out = (g[c] + sigmoid(yb[p])) * x ; overlaps with in-flight cp.async
        const int base4 = tile * TP4;
        const float4* cur4 = (const float4*)cur;
#pragma unroll
        for (int j = 0; j < 16; j++) {
            int i4 = t + j * K3T;
            int c = i4 / TP4, p4 = i4 % TP4;
            if (base4 + p4 < HW4) {
                float4 xv = cur4[i4];
                const float gv = sg[c];
                const int p = p4 * 4;
                float4 o;
                o.x = (gv + sy[p + 0]) * xv.x;
                o.y = (gv + sy[p + 1]) * xv.y;
                o.z = (gv + sy[p + 2]) * xv.z;
                o.w = (gv + sy[p + 3]) * xv.w;
                out4[(size_t)c * HW4 + base4 + p4] = o;
            }
        }
        __syncthreads();   // buffer-reuse safety before refilling `cur`
        tile = ntile;
        i++;
    }
}

// ---------------- Launch ----------------------------------------------------------
extern "C" void kernel_launch(void* const* d_in, const int* in_sizes, int n_in,
                              void* d_out, int out_size) {
    const float* x    = (const float*)d_in[0];
    const float* cv1w = (const float*)d_in[1];
    const float* cv1b = (const float*)d_in[2];
    // d_in[3], d_in[4] = ch_cv2_w/b : mathematically unused (softmax over size-1 dim)
    const float* cv3w = (const float*)d_in[5];
    const float* cv3b = (const float*)d_in[6];
    const float* lng  = (const float*)d_in[7];
    const float* lnb  = (const float*)d_in[8];
    const float* sp1w = (const float*)d_in[9];
    const float* sp1b = (const float*)d_in[10];
    const float* sp2w = (const float*)d_in[11];
    const float* sp2b = (const float*)d_in[12];

    int nsm = 148;
    cudaDeviceGetAttribute(&nsm, cudaDevAttrMultiProcessorCount, 0);

    dim3 g1(SEGS, C);
    k1_sums<<<g1, 256>>>((const float4*)x);
    k2_scalars<<<1, 256>>>(cv1w, cv1b, cv3w, cv3b, lng, lnb, sp1w, sp1b, sp2w, sp2b);

    const int smem_bytes = (2 * TILE_F + C + C + K3T + TP) * (int)sizeof(float);
    cudaFuncSetAttribute(k3_out, cudaFuncAttributeMaxDynamicSharedMemorySize, smem_bytes);
    k3_out<<<nsm, K3T, smem_bytes>>>((const float4*)x, (float4*)d_out, nsm);
}